// round 13
// baseline (speedup 1.0000x reference)
#include <cuda_runtime.h>
#include <cuda_fp16.h>
#include <cstdint>

#define DIN 1024
#define HD  128
#define BM  64
#define KC  32
#define NCHUNK (DIN/KC)   // 32
#define THREADS 256

// ---------------- preconverted weights (transposed, single fp16) -----------
__device__ __half g_W0T[HD*DIN];
__device__ __half g_W1T[HD*HD];
__device__ __half g_W2T[HD*HD];

// WT[n][k] = fp16(W[k][n])
__global__ void prep_w(const float* __restrict__ W, int K, int which)
{
    __shared__ float t[32][33];
    __half* dst = which==0 ? g_W0T : (which==1 ? g_W1T : g_W2T);
    int bx = blockIdx.x, by = blockIdx.y;
    int tx = threadIdx.x, ty = threadIdx.y;   // (32,8)
    #pragma unroll
    for (int r = 0; r < 32; r += 8)
        t[ty+r][tx] = W[(size_t)(bx*32 + ty + r)*HD + by*32 + tx];
    __syncthreads();
    #pragma unroll
    for (int r = 0; r < 32; r += 8) {
        int n = by*32 + ty + r;
        int k = bx*32 + tx;
        dst[(size_t)n*K + k] = __float2half_rn(t[tx][ty+r]);
    }
}

// ---------------- helpers ---------------------------------------------------
__device__ __forceinline__ uint32_t smem_u32(const void* p) {
    uint32_t a;
    asm("{ .reg .u64 t; cvta.to.shared.u64 t, %1; cvt.u32.u64 %0, t; }" : "=r"(a) : "l"(p));
    return a;
}
__device__ __forceinline__ uint32_t sw64 (uint32_t o) { return o ^ ((o >> 3) & 0x30); } // 64B rows
__device__ __forceinline__ uint32_t sw128(uint32_t o) { return o ^ ((o >> 3) & 0x70); } // 128B rows
__device__ __forceinline__ uint32_t sw256(uint32_t o) { return o ^ ((o >> 4) & 0x70); } // 256B rows

__device__ __forceinline__ void cpasync16(uint32_t dst, const void* src) {
    asm volatile("cp.async.cg.shared.global [%0], [%1], 16;" :: "r"(dst), "l"(src));
}
#define CP_COMMIT()  asm volatile("cp.async.commit_group;" ::: "memory")
#define CP_WAIT0()   asm volatile("cp.async.wait_group 0;"  ::: "memory")
#define CP_WAIT1()   asm volatile("cp.async.wait_group 1;"  ::: "memory")
#define CP_WAIT2()   asm volatile("cp.async.wait_group 2;"  ::: "memory")

__device__ __forceinline__ void ldsm4(uint32_t addr, uint32_t* r) {
    asm volatile("ldmatrix.sync.aligned.m8n8.x4.shared.b16 {%0,%1,%2,%3}, [%4];"
        : "=r"(r[0]), "=r"(r[1]), "=r"(r[2]), "=r"(r[3]) : "r"(addr));
}
__device__ __forceinline__ void mma16816(float* c, const uint32_t* a, uint32_t b0, uint32_t b1) {
    asm volatile("mma.sync.aligned.m16n8k16.row.col.f32.f16.f16.f32 "
        "{%0,%1,%2,%3}, {%4,%5,%6,%7}, {%8,%9}, {%0,%1,%2,%3};"
        : "+f"(c[0]), "+f"(c[1]), "+f"(c[2]), "+f"(c[3])
        : "r"(a[0]), "r"(a[1]), "r"(a[2]), "r"(a[3]), "r"(b0), "r"(b1));
}

// ---------------- smem layout (~55KB) ---------------------------------------
// GEMM0: B ring 5 stages x 8KB at [0,40K): 128 n-rows x 64B fp16, sw64.
//        A ring 3 slots x 4KB at [40K,52K): 64 rows x 64B fp16, sw64.
// Phase2 overlay: h (64 rows x 256B fp16, sw256) at 0 (16KB);
//        WB0 @16K, WB1 @32K (128 n-rows x 128B fp16, sw128), 16KB each.
#define SB(s)    ((uint32_t)(s) * 8192u)
#define ASLOT(a) (40960u + (uint32_t)(a) * 4096u)
#define H_OFF    0
#define WB0      16384
#define WB1      32768
#define S_BIAS   53248
#define S_PART   54784
#define SMEM_TOTAL 55808

__global__ __launch_bounds__(256, 3)
void fused_mlp_v13(const float* __restrict__ x,
                   const float* __restrict__ b0,
                   const float* __restrict__ b1,
                   const float* __restrict__ b2,
                   float* __restrict__ out)
{
    extern __shared__ char smem[];
    const uint32_t su = smem_u32(smem);
    const int tid  = threadIdx.x;
    const int lane = tid & 31;
    const int wid  = tid >> 5;       // 8 warps: 2 in M x 4 in N
    const int wm   = wid & 1;        // rows wm*32..+32
    const int wn   = wid >> 1;       // cols wn*32..+32
    const int m0   = blockIdx.x * BM;

    float* b0s = (float*)(smem + S_BIAS);
    float* b1s = (float*)(smem + S_BIAS + 512);
    float* b2s = (float*)(smem + S_BIAS + 1024);
    float* part = (float*)(smem + S_PART);   // [4][64]
    if (tid < HD) { b0s[tid] = b0[tid]; b1s[tid] = b1[tid]; b2s[tid] = b2[tid]; }

    const uint32_t aLane   = (uint32_t)(lane & 15);
    const uint32_t aColSel = (uint32_t)((lane >> 4) * 16);
    const uint32_t bRow    = (uint32_t)((lane & 7) + ((lane >> 4) & 1) * 8);
    const uint32_t bColSel = (uint32_t)(((lane >> 3) & 1) * 16);
    const int colbase = (lane & 3) * 2;
    const int qr = lane >> 2;

    // per-thread x staging: 2 float4 = 8 floats of one chunk
    const int xrow = tid >> 2;               // used by ldg/sts pair below
    float4 xr0, xr1;

    float acc[2][4][4];
    auto zero_acc = [&]() {
        #pragma unroll
        for (int a = 0; a < 2; a++)
            #pragma unroll
            for (int n = 0; n < 4; n++)
                #pragma unroll
                for (int q = 0; q < 4; q++) acc[a][n][q] = 0.f;
    };
    zero_acc();

    // ---- loaders ------------------------------------------------------------
    // x chunk: 64 rows x 32 floats. thread t: row = t>>2, 32B-group = t&3.
    auto ldg_x = [&](int chunk) {
        const float* xp = x + (size_t)(m0 + xrow) * DIN + chunk * KC + (tid & 3) * 8;
        xr0 = *(const float4*)(xp);
        xr1 = *(const float4*)(xp + 4);
    };
    auto sts_A = [&](int slot) {
        __half2 h0 = __floats2half2_rn(xr0.x, xr0.y);
        __half2 h1 = __floats2half2_rn(xr0.z, xr0.w);
        __half2 h2 = __floats2half2_rn(xr1.x, xr1.y);
        __half2 h3 = __floats2half2_rn(xr1.z, xr1.w);
        uint4 v = { *(uint32_t*)&h0, *(uint32_t*)&h1, *(uint32_t*)&h2, *(uint32_t*)&h3 };
        *(uint4*)(smem + ASLOT(slot) + sw64((uint32_t)(xrow*64 + (tid & 3)*16))) = v;
    };
    auto cp_B = [&](int chunk, int stg) {
        const __half* wb = g_W0T + chunk * KC;
        #pragma unroll
        for (int j = 0; j < 2; j++) {
            int flat = j * 256 + tid;         // 0..511
            int row = flat >> 2, g = flat & 3;
            cpasync16(su + SB(stg) + sw64((uint32_t)(row*64 + g*16)),
                      wb + (size_t)row * DIN + g*8);
        }
        CP_COMMIT();
    };
    auto cp_Whalf = [&](const __half* src, int half, uint32_t dstb) {
        #pragma unroll
        for (int j = 0; j < 4; j++) {
            int flat = j * 256 + tid;         // 0..1023
            int row = flat >> 3, g = flat & 7;
            cpasync16(su + dstb + sw128((uint32_t)(row*128 + g*16)),
                      src + (size_t)row * HD + half*64 + g*8);
        }
        CP_COMMIT();
    };

    // GEMM0 compute for chunk at B stage sB, A slot sA
    auto compute_g0 = [&](int sB, int sA) {
        uint32_t ab = su + ASLOT(sA);
        uint32_t bb = su + SB(sB);
        #pragma unroll
        for (int ks = 0; ks < 2; ks++) {
            uint32_t af[2][4];
            #pragma unroll
            for (int mi = 0; mi < 2; mi++)
                ldsm4(ab + sw64((uint32_t)(wm*32 + mi*16 + aLane)*64 + (uint32_t)ks*32 + aColSel), af[mi]);
            #pragma unroll
            for (int nn = 0; nn < 2; nn++) {
                uint32_t bf[4];
                ldsm4(bb + sw64((uint32_t)(wn*32 + nn*16 + bRow)*64 + (uint32_t)ks*32 + bColSel), bf);
                #pragma unroll
                for (int mi = 0; mi < 2; mi++) {
                    mma16816(acc[mi][nn*2],   af[mi], bf[0], bf[1]);
                    mma16816(acc[mi][nn*2+1], af[mi], bf[2], bf[3]);
                }
            }
        }
    };
    // GEMM1/2: A = h (256B rows), B = W half buffer (128B rows), 4 ksteps
    auto compute_g12 = [&](uint32_t wbase, uint32_t kbyte) {
        #pragma unroll
        for (int ks = 0; ks < 4; ks++) {
            uint32_t af[2][4];
            #pragma unroll
            for (int mi = 0; mi < 2; mi++)
                ldsm4(su + H_OFF + sw256((uint32_t)(wm*32 + mi*16 + aLane)*256 + kbyte + (uint32_t)ks*32 + aColSel), af[mi]);
            #pragma unroll
            for (int nn = 0; nn < 2; nn++) {
                uint32_t bf[4];
                ldsm4(su + wbase + sw128((uint32_t)(wn*32 + nn*16 + bRow)*128 + (uint32_t)ks*32 + bColSel), bf);
                #pragma unroll
                for (int mi = 0; mi < 2; mi++) {
                    mma16816(acc[mi][nn*2],   af[mi], bf[0], bf[1]);
                    mma16816(acc[mi][nn*2+1], af[mi], bf[2], bf[3]);
                }
            }
        }
    };

    // ---- GEMM0 prologue -----------------------------------------------------
    cp_B(0, 0); cp_B(1, 1); cp_B(2, 2);      // 3 groups in flight
    ldg_x(0);
    CP_WAIT2();                               // B(0) arrived
    __syncthreads();                          // B(0) + biases visible
    sts_A(0);
    ldg_x(1);
    __syncthreads();                          // A(0) visible

    // ---- GEMM0 mainloop: ONE sync per iteration ----------------------------
    // rings: B stage i%5 (commit i+3), A slot i%3 (write i+1)
    {
        int sB = 0, sA = 0;                   // read cursors (i%5, i%3)
        int cB = 3;                           // commit cursor ((i+3)%5)
        int wA = 1;                           // write cursor ((i+1)%3)
        for (int i = 0; i < NCHUNK; i++) {
            if (i + 3 < NCHUNK) {
                cp_B(i + 3, cB);
                if (++cB == 5) cB = 0;
            }
            if (i + 1 < NCHUNK) {
                sts_A(wA);                    // chunk i+1 from registers
                if (++wA == 3) wA = 0;
                if (i + 2 < NCHUNK) ldg_x(i + 2);
                if      (i + 3 < NCHUNK) CP_WAIT2();
                else if (i + 2 < NCHUNK) CP_WAIT1();
                else                     CP_WAIT0();
            }
            __syncthreads();                  // publish A(i+1), B(i+1)
            compute_g0(sB, sA);
            if (++sB == 5) sB = 0;
            if (++sA == 3) sA = 0;
        }
    }
    __syncthreads();                          // all warps done with rings

    // ---- prefetch W1 halves (overlap epilogue 0) ----------------------------
    cp_Whalf(g_W1T, 0, WB0);
    cp_Whalf(g_W1T, 1, WB1);

    // ---- epilogue 0: bias + rmsnorm; h -> smem fp16 (256B rows) -------------
    {
        float ssp[4] = {0.f, 0.f, 0.f, 0.f};
        #pragma unroll
        for (int mi = 0; mi < 2; mi++)
            #pragma unroll
            for (int n8 = 0; n8 < 4; n8++) {
                float2 bv = *(float2*)&b0s[wn*32 + n8*8 + colbase];
                float* c = acc[mi][n8];
                c[0] += bv.x; c[1] += bv.y; c[2] += bv.x; c[3] += bv.y;
                ssp[mi*2]   = fmaf(c[0], c[0], fmaf(c[1], c[1], ssp[mi*2]));
                ssp[mi*2+1] = fmaf(c[2], c[2], fmaf(c[3], c[3], ssp[mi*2+1]));
            }
        #pragma unroll
        for (int i = 0; i < 4; i++) {
            ssp[i] += __shfl_xor_sync(0xffffffffu, ssp[i], 1);
            ssp[i] += __shfl_xor_sync(0xffffffffu, ssp[i], 2);
        }
        if ((lane & 3) == 0) {
            #pragma unroll
            for (int i = 0; i < 4; i++) {
                int r = wm*32 + (i >> 1)*16 + (i & 1)*8 + qr;
                part[wn*64 + r] = ssp[i];
            }
        }
        __syncthreads();
        #pragma unroll
        for (int i = 0; i < 4; i++) {
            int r = wm*32 + (i >> 1)*16 + (i & 1)*8 + qr;
            float ss = part[r] + part[64 + r] + part[128 + r] + part[192 + r];
            float sc = rsqrtf(ss * (1.f/128.f) + 1e-6f);
            int mi = i >> 1, half = i & 1;
            #pragma unroll
            for (int n8 = 0; n8 < 4; n8++) {
                float v0 = acc[mi][n8][half*2]     * sc;
                float v1 = acc[mi][n8][half*2 + 1] * sc;
                __half2 h2 = __floats2half2_rn(v0, v1);
                int col = wn*32 + n8*8 + colbase;
                *(uint32_t*)(smem + H_OFF + sw256((uint32_t)(r*256 + col*2))) = *(uint32_t*)&h2;
            }
        }
    }
    CP_WAIT1();               // W1 half0 in
    __syncthreads();          // h + WB0 visible

    // ---- GEMM1 --------------------------------------------------------------
    zero_acc();
    compute_g12(WB0, 0);
    __syncthreads();          // WB0 free
    cp_Whalf(g_W2T, 0, WB0);
    CP_WAIT1();               // W1 half1 in
    __syncthreads();
    compute_g12(WB1, 128);
    __syncthreads();          // WB1 free; h reads done
    cp_Whalf(g_W2T, 1, WB1);

    // ---- epilogue 1: sigmoid + residual; h rewritten in place ---------------
    #pragma unroll
    for (int mi = 0; mi < 2; mi++)
        #pragma unroll
        for (int half = 0; half < 2; half++) {
            int r = wm*32 + mi*16 + half*8 + qr;
            #pragma unroll
            for (int n8 = 0; n8 < 4; n8++) {
                int col = wn*32 + n8*8 + colbase;
                float2 bv = *(float2*)&b1s[col];
                uint32_t off = sw256((uint32_t)(r*256 + col*2));
                uint32_t hu = *(uint32_t*)(smem + H_OFF + off);
                __half2 hb = *(__half2*)&hu;
                float r0 = __low2float(hb), r1 = __high2float(hb);
                float v0 = 1.f / (1.f + __expf(-(acc[mi][n8][half*2]     + bv.x))) + r0;
                float v1 = 1.f / (1.f + __expf(-(acc[mi][n8][half*2 + 1] + bv.y))) + r1;
                __half2 h2 = __floats2half2_rn(v0, v1);
                *(uint32_t*)(smem + H_OFF + off) = *(uint32_t*)&h2;
            }
        }
    CP_WAIT1();               // W2 half0 in
    __syncthreads();          // h1 + WB0 visible

    // ---- GEMM2 --------------------------------------------------------------
    zero_acc();
    compute_g12(WB0, 0);
    CP_WAIT0();               // W2 half1 in
    __syncthreads();
    compute_g12(WB1, 128);

    // ---- epilogue 2: relu + residual; store ---------------------------------
    #pragma unroll
    for (int mi = 0; mi < 2; mi++)
        #pragma unroll
        for (int half = 0; half < 2; half++) {
            int r = wm*32 + mi*16 + half*8 + qr;
            float* orow = out + (size_t)(m0 + r) * HD;
            #pragma unroll
            for (int n8 = 0; n8 < 4; n8++) {
                int col = wn*32 + n8*8 + colbase;
                float2 bv = *(float2*)&b2s[col];
                uint32_t hu = *(uint32_t*)(smem + H_OFF + sw256((uint32_t)(r*256 + col*2)));
                __half2 hb = *(__half2*)&hu;
                float2 o;
                o.x = fmaxf(acc[mi][n8][half*2]     + bv.x, 0.f) + __low2float(hb);
                o.y = fmaxf(acc[mi][n8][half*2 + 1] + bv.y, 0.f) + __high2float(hb);
                *(float2*)(orow + col) = o;
            }
        }
}

// ---------------- launch ----------------------------------------------------
extern "C" void kernel_launch(void* const* d_in, const int* in_sizes, int n_in,
                              void* d_out, int out_size)
{
    const float* x  = (const float*)d_in[0];
    const float* W0 = (const float*)d_in[1];
    const float* b0 = (const float*)d_in[2];
    const float* W1 = (const float*)d_in[3];
    const float* b1 = (const float*)d_in[4];
    const float* W2 = (const float*)d_in[5];
    const float* b2 = (const float*)d_in[6];
    float* out = (float*)d_out;

    const int M = in_sizes[0] / DIN;   // 32768

    prep_w<<<dim3(DIN/32, HD/32), dim3(32, 8)>>>(W0, DIN, 0);
    prep_w<<<dim3(HD/32,  HD/32), dim3(32, 8)>>>(W1, HD, 1);
    prep_w<<<dim3(HD/32,  HD/32), dim3(32, 8)>>>(W2, HD, 2);

    cudaFuncSetAttribute(fused_mlp_v13,
                         cudaFuncAttributeMaxDynamicSharedMemorySize, SMEM_TOTAL);
    fused_mlp_v13<<<M / BM, THREADS, SMEM_TOTAL>>>(x, b0, b1, b2, out);
}

// round 15
// speedup vs baseline: 1.4516x; 1.4516x over previous
#include <cuda_runtime.h>
#include <cuda_fp16.h>
#include <cstdint>

#define DIN 1024
#define HD  128
#define BM  64
#define KC  32
#define NCHUNK (DIN/KC)   // 32
#define THREADS 128

// ---------------- preconverted weights (transposed, single fp16) -----------
__device__ __half g_W0T[HD*DIN];
__device__ __half g_W1T[HD*HD];
__device__ __half g_W2T[HD*HD];

// WT[n][k] = fp16(W[k][n])
__global__ void prep_w(const float* __restrict__ W, int K, int which)
{
    __shared__ float t[32][33];
    __half* dst = which==0 ? g_W0T : (which==1 ? g_W1T : g_W2T);
    int bx = blockIdx.x, by = blockIdx.y;
    int tx = threadIdx.x, ty = threadIdx.y;   // (32,8)
    #pragma unroll
    for (int r = 0; r < 32; r += 8)
        t[ty+r][tx] = W[(size_t)(bx*32 + ty + r)*HD + by*32 + tx];
    __syncthreads();
    #pragma unroll
    for (int r = 0; r < 32; r += 8) {
        int n = by*32 + ty + r;
        int k = bx*32 + tx;
        dst[(size_t)n*K + k] = __float2half_rn(t[tx][ty+r]);
    }
}

// ---------------- helpers ---------------------------------------------------
__device__ __forceinline__ uint32_t smem_u32(const void* p) {
    uint32_t a;
    asm("{ .reg .u64 t; cvta.to.shared.u64 t, %1; cvt.u32.u64 %0, t; }" : "=r"(a) : "l"(p));
    return a;
}
__device__ __forceinline__ uint32_t sw64 (uint32_t o) { return o ^ ((o >> 3) & 0x30); } // 64B rows
__device__ __forceinline__ uint32_t sw128(uint32_t o) { return o ^ ((o >> 3) & 0x70); } // 128B rows
__device__ __forceinline__ uint32_t sw256(uint32_t o) { return o ^ ((o >> 4) & 0x70); } // 256B rows

__device__ __forceinline__ void cpasync16(uint32_t dst, const void* src) {
    asm volatile("cp.async.cg.shared.global [%0], [%1], 16;" :: "r"(dst), "l"(src));
}
#define CP_COMMIT()  asm volatile("cp.async.commit_group;" ::: "memory")
#define CP_WAIT0()   asm volatile("cp.async.wait_group 0;"  ::: "memory")
#define CP_WAIT1()   asm volatile("cp.async.wait_group 1;"  ::: "memory")

__device__ __forceinline__ void ldsm4(uint32_t addr, uint32_t* r) {
    asm volatile("ldmatrix.sync.aligned.m8n8.x4.shared.b16 {%0,%1,%2,%3}, [%4];"
        : "=r"(r[0]), "=r"(r[1]), "=r"(r[2]), "=r"(r[3]) : "r"(addr));
}
__device__ __forceinline__ void mma16816(float* c, const uint32_t* a, uint32_t b0, uint32_t b1) {
    asm volatile("mma.sync.aligned.m16n8k16.row.col.f32.f16.f16.f32 "
        "{%0,%1,%2,%3}, {%4,%5,%6,%7}, {%8,%9}, {%0,%1,%2,%3};"
        : "+f"(c[0]), "+f"(c[1]), "+f"(c[2]), "+f"(c[3])
        : "r"(a[0]), "r"(a[1]), "r"(a[2]), "r"(a[3]), "r"(b0), "r"(b1));
}

// ---------------- smem layout (56KB -> 4 CTAs/SM) ---------------------------
// GEMM0: 3 stages x 16KB at [0,48K): x fp32 (64 rows x 128B, sw128) at +0,
//        B fp16 (128 n-rows x 64B, sw64) at +8K.
//        A double buffer 2 x 4KB at [48K+1K pad ... actually 49152,57344):
//        64 rows x 64B fp16, sw64.
// Phase2 overlay: h (64 rows x 256B fp16, sw256) at 0 (16KB);
//        WB0 @16384, WB1 @32768 (128 n-rows x 128B fp16, sw128), 16KB each
//        -> WB1 ends at 49152.
//        part (rmsnorm partials, 512B) at 49152 = A-slot region, which is
//        dead once GEMM0 finished. (Round-14 bug: part@48128 was INSIDE WB1.)
#define STG(s)   ((uint32_t)(s) * 16384u)
#define X_OFF    0
#define B_OFF    8192
#define ASLOT(a) (49152u + (uint32_t)(a) * 4096u)
#define H_OFF    0
#define WB0      16384
#define WB1      32768
#define S_PART   49152
#define SMEM_TOTAL 57344

__global__ __launch_bounds__(128, 4)
void fused_mlp_v15(const float* __restrict__ x,
                   const float* __restrict__ b0,
                   const float* __restrict__ b1,
                   const float* __restrict__ b2,
                   float* __restrict__ out)
{
    extern __shared__ char smem[];
    const uint32_t su = smem_u32(smem);
    const int tid  = threadIdx.x;
    const int lane = tid & 31;
    const int wid  = tid >> 5;       // 4 warps: 2 in M x 2 in N
    const int wm   = wid & 1;        // rows wm*32..+32
    const int wn   = wid >> 1;       // cols wn*64..+64
    const int m0   = blockIdx.x * BM;

    float* part = (float*)(smem + S_PART);   // [2][64] floats, phase-2 only

    const uint32_t aLane   = (uint32_t)(lane & 15);
    const uint32_t aColSel = (uint32_t)((lane >> 4) * 16);
    const uint32_t bRow    = (uint32_t)((lane & 7) + ((lane >> 4) & 1) * 8);
    const uint32_t bColSel = (uint32_t)(((lane >> 3) & 1) * 16);
    const int colbase = (lane & 3) * 2;
    const int qr = lane >> 2;

    float acc[2][8][4];     // [mtile][n8][quad] : warp tile m32 x n64
    auto zero_acc = [&]() {
        #pragma unroll
        for (int a = 0; a < 2; a++)
            #pragma unroll
            for (int n = 0; n < 8; n++)
                #pragma unroll
                for (int q = 0; q < 4; q++) acc[a][n][q] = 0.f;
    };
    zero_acc();

    // ---- async loaders ------------------------------------------------------
    auto cp_chunk = [&](int chunk, int stg) {
        uint32_t sb = STG(stg);
        const float* xb = x + (size_t)m0 * DIN + chunk * KC;
        #pragma unroll
        for (int j = 0; j < 4; j++) {
            int flat = j * 128 + tid;         // 0..511
            int row = flat >> 3, c = flat & 7;
            cpasync16(su + sb + X_OFF + sw128((uint32_t)(row*128 + c*16)),
                      xb + (size_t)row * DIN + c*4);
        }
        const __half* wb = g_W0T + chunk * KC;
        #pragma unroll
        for (int j = 0; j < 4; j++) {
            int flat = j * 128 + tid;         // 0..511
            int row = flat >> 2, g = flat & 3;
            cpasync16(su + sb + B_OFF + sw64((uint32_t)(row*64 + g*16)),
                      wb + (size_t)row * DIN + g*8);
        }
        CP_COMMIT();
    };
    auto cp_Whalf = [&](const __half* src, int half, uint32_t dstb) {
        #pragma unroll
        for (int j = 0; j < 8; j++) {
            int flat = j * 128 + tid;         // 0..1023
            int row = flat >> 3, g = flat & 7;
            cpasync16(su + dstb + sw128((uint32_t)(row*128 + g*16)),
                      src + (size_t)row * HD + half*64 + g*8);
        }
        CP_COMMIT();
    };

    // convert one x chunk (fp32 in stage) -> fp16 A slot. 16 floats/thread.
    auto convert_x = [&](int stg, int slot) {
        uint32_t xb = STG(stg) + X_OFF;
        uint32_t ab = ASLOT(slot);
        int row = tid >> 1, c = tid & 1;
        uint32_t so = (uint32_t)(row*128 + c*64);
        float4 f0 = *(const float4*)(smem + xb + sw128(so));
        float4 f1 = *(const float4*)(smem + xb + sw128(so + 16));
        float4 f2 = *(const float4*)(smem + xb + sw128(so + 32));
        float4 f3 = *(const float4*)(smem + xb + sw128(so + 48));
        __half2 h0 = __floats2half2_rn(f0.x, f0.y), h1 = __floats2half2_rn(f0.z, f0.w);
        __half2 h2 = __floats2half2_rn(f1.x, f1.y), h3 = __floats2half2_rn(f1.z, f1.w);
        __half2 h4 = __floats2half2_rn(f2.x, f2.y), h5 = __floats2half2_rn(f2.z, f2.w);
        __half2 h6 = __floats2half2_rn(f3.x, f3.y), h7 = __floats2half2_rn(f3.z, f3.w);
        uint4 v0 = { *(uint32_t*)&h0, *(uint32_t*)&h1, *(uint32_t*)&h2, *(uint32_t*)&h3 };
        uint4 v1 = { *(uint32_t*)&h4, *(uint32_t*)&h5, *(uint32_t*)&h6, *(uint32_t*)&h7 };
        *(uint4*)(smem + ab + sw64((uint32_t)(row*64 + c*32)))      = v0;
        *(uint4*)(smem + ab + sw64((uint32_t)(row*64 + c*32 + 16))) = v1;
    };

    // GEMM0 compute: B stage stg, A slot slot. warp: m32 x n64, k32
    auto compute_g0 = [&](int stg, int slot) {
        uint32_t ab = su + ASLOT(slot);
        uint32_t bb = su + STG(stg) + B_OFF;
        #pragma unroll
        for (int ks = 0; ks < 2; ks++) {
            uint32_t af[2][4];
            #pragma unroll
            for (int mi = 0; mi < 2; mi++)
                ldsm4(ab + sw64((uint32_t)(wm*32 + mi*16 + aLane)*64 + (uint32_t)ks*32 + aColSel), af[mi]);
            #pragma unroll
            for (int nn = 0; nn < 4; nn++) {
                uint32_t bf[4];
                ldsm4(bb + sw64((uint32_t)(wn*64 + nn*16 + bRow)*64 + (uint32_t)ks*32 + bColSel), bf);
                #pragma unroll
                for (int mi = 0; mi < 2; mi++) {
                    mma16816(acc[mi][nn*2],   af[mi], bf[0], bf[1]);
                    mma16816(acc[mi][nn*2+1], af[mi], bf[2], bf[3]);
                }
            }
        }
    };
    // GEMM1/2: A = h (256B rows), B = W half buffer (128B rows), 4 ksteps
    auto compute_g12 = [&](uint32_t wbase, uint32_t kbyte) {
        #pragma unroll
        for (int ks = 0; ks < 4; ks++) {
            uint32_t af[2][4];
            #pragma unroll
            for (int mi = 0; mi < 2; mi++)
                ldsm4(su + H_OFF + sw256((uint32_t)(wm*32 + mi*16 + aLane)*256 + kbyte + (uint32_t)ks*32 + aColSel), af[mi]);
            #pragma unroll
            for (int nn = 0; nn < 4; nn++) {
                uint32_t bf[4];
                ldsm4(su + wbase + sw128((uint32_t)(wn*64 + nn*16 + bRow)*128 + (uint32_t)ks*32 + bColSel), bf);
                #pragma unroll
                for (int mi = 0; mi < 2; mi++) {
                    mma16816(acc[mi][nn*2],   af[mi], bf[0], bf[1]);
                    mma16816(acc[mi][nn*2+1], af[mi], bf[2], bf[3]);
                }
            }
        }
    };

    // ---- GEMM0: 3-stage ring, commit 2 ahead, 2 syncs/iter ------------------
    cp_chunk(0, 0);
    cp_chunk(1, 1);
    CP_WAIT1();               // chunk 0 arrived
    __syncthreads();
    convert_x(0, 0);

    {
        int sC = 2, sR = 0;   // commit / read stage cursors
        for (int i = 0; i < NCHUNK; i++) {
            if (i + 2 < NCHUNK) {
                cp_chunk(i + 2, sC);
                if (++sC == 3) sC = 0;
            }
            if (i + 1 < NCHUNK) {
                if (i + 2 < NCHUNK) CP_WAIT1(); else CP_WAIT0();
                __syncthreads();                  // publish x(i+1), A(i)
                int st = sR + 1; if (st == 3) st = 0;
                convert_x(st, (i + 1) & 1);       // A(i+1), other slot
            }
            compute_g0(sR, i & 1);
            if (++sR == 3) sR = 0;
            __syncthreads();                      // A(i+1) done; stage i free
        }
    }

    // ---- prefetch W1 halves (overlap epilogue 0) ----------------------------
    cp_Whalf(g_W1T, 0, WB0);
    cp_Whalf(g_W1T, 1, WB1);

    // ---- epilogue 0: bias + rmsnorm; h -> smem fp16 (256B rows) -------------
    {
        float ssp[4] = {0.f, 0.f, 0.f, 0.f};   // [mi*2+half]
        #pragma unroll
        for (int mi = 0; mi < 2; mi++)
            #pragma unroll
            for (int n8 = 0; n8 < 8; n8++) {
                float2 bv = *(const float2*)&b0[wn*64 + n8*8 + colbase];
                float* c = acc[mi][n8];
                c[0] += bv.x; c[1] += bv.y; c[2] += bv.x; c[3] += bv.y;
                ssp[mi*2]   = fmaf(c[0], c[0], fmaf(c[1], c[1], ssp[mi*2]));
                ssp[mi*2+1] = fmaf(c[2], c[2], fmaf(c[3], c[3], ssp[mi*2+1]));
            }
        #pragma unroll
        for (int i = 0; i < 4; i++) {
            ssp[i] += __shfl_xor_sync(0xffffffffu, ssp[i], 1);
            ssp[i] += __shfl_xor_sync(0xffffffffu, ssp[i], 2);
        }
        if ((lane & 3) == 0) {
            #pragma unroll
            for (int i = 0; i < 4; i++) {
                int r = wm*32 + (i >> 1)*16 + (i & 1)*8 + qr;
                part[wn*64 + r] = ssp[i];
            }
        }
        __syncthreads();
        #pragma unroll
        for (int i = 0; i < 4; i++) {
            int r = wm*32 + (i >> 1)*16 + (i & 1)*8 + qr;
            float ss = part[r] + part[64 + r];
            float sc = rsqrtf(ss * (1.f/128.f) + 1e-6f);
            int mi = i >> 1, half = i & 1;
            #pragma unroll
            for (int n8 = 0; n8 < 8; n8++) {
                float v0 = acc[mi][n8][half*2]     * sc;
                float v1 = acc[mi][n8][half*2 + 1] * sc;
                __half2 h2 = __floats2half2_rn(v0, v1);
                int col = wn*64 + n8*8 + colbase;
                *(uint32_t*)(smem + H_OFF + sw256((uint32_t)(r*256 + col*2))) = *(uint32_t*)&h2;
            }
        }
    }
    CP_WAIT1();               // W1 half0 in
    __syncthreads();          // h + WB0 visible

    // ---- GEMM1 --------------------------------------------------------------
    zero_acc();
    compute_g12(WB0, 0);
    __syncthreads();          // WB0 free
    cp_Whalf(g_W2T, 0, WB0);
    CP_WAIT1();               // W1 half1 in
    __syncthreads();
    compute_g12(WB1, 128);
    __syncthreads();          // WB1 free; h reads done
    cp_Whalf(g_W2T, 1, WB1);

    // ---- epilogue 1: sigmoid + residual; h rewritten in place ---------------
    #pragma unroll
    for (int mi = 0; mi < 2; mi++)
        #pragma unroll
        for (int half = 0; half < 2; half++) {
            int r = wm*32 + mi*16 + half*8 + qr;
            #pragma unroll
            for (int n8 = 0; n8 < 8; n8++) {
                int col = wn*64 + n8*8 + colbase;
                float2 bv = *(const float2*)&b1[col];
                uint32_t off = sw256((uint32_t)(r*256 + col*2));
                uint32_t hu = *(uint32_t*)(smem + H_OFF + off);
                __half2 hb = *(__half2*)&hu;
                float r0 = __low2float(hb), r1 = __high2float(hb);
                float v0 = 1.f / (1.f + __expf(-(acc[mi][n8][half*2]     + bv.x))) + r0;
                float v1 = 1.f / (1.f + __expf(-(acc[mi][n8][half*2 + 1] + bv.y))) + r1;
                __half2 h2 = __floats2half2_rn(v0, v1);
                *(uint32_t*)(smem + H_OFF + off) = *(uint32_t*)&h2;
            }
        }
    CP_WAIT1();               // W2 half0 in
    __syncthreads();          // h1 + WB0 visible

    // ---- GEMM2 --------------------------------------------------------------
    zero_acc();
    compute_g12(WB0, 0);
    CP_WAIT0();               // W2 half1 in
    __syncthreads();
    compute_g12(WB1, 128);

    // ---- epilogue 2: relu + residual; store ---------------------------------
    #pragma unroll
    for (int mi = 0; mi < 2; mi++)
        #pragma unroll
        for (int half = 0; half < 2; half++) {
            int r = wm*32 + mi*16 + half*8 + qr;
            float* orow = out + (size_t)(m0 + r) * HD;
            #pragma unroll
            for (int n8 = 0; n8 < 8; n8++) {
                int col = wn*64 + n8*8 + colbase;
                float2 bv = *(const float2*)&b2[col];
                uint32_t hu = *(uint32_t*)(smem + H_OFF + sw256((uint32_t)(r*256 + col*2)));
                __half2 hb = *(__half2*)&hu;
                float2 o;
                o.x = fmaxf(acc[mi][n8][half*2]     + bv.x, 0.f) + __low2float(hb);
                o.y = fmaxf(acc[mi][n8][half*2 + 1] + bv.y, 0.f) + __high2float(hb);
                *(float2*)(orow + col) = o;
            }
        }
}

// ---------------- launch ----------------------------------------------------
extern "C" void kernel_launch(void* const* d_in, const int* in_sizes, int n_in,
                              void* d_out, int out_size)
{
    const float* x  = (const float*)d_in[0];
    const float* W0 = (const float*)d_in[1];
    const float* b0 = (const float*)d_in[2];
    const float* W1 = (const float*)d_in[3];
    const float* b1 = (const float*)d_in[4];
    const float* W2 = (const float*)d_in[5];
    const float* b2 = (const float*)d_in[6];
    float* out = (float*)d_out;

    const int M = in_sizes[0] / DIN;   // 32768

    prep_w<<<dim3(DIN/32, HD/32), dim3(32, 8)>>>(W0, DIN, 0);
    prep_w<<<dim3(HD/32,  HD/32), dim3(32, 8)>>>(W1, HD, 1);
    prep_w<<<dim3(HD/32,  HD/32), dim3(32, 8)>>>(W2, HD, 2);

    cudaFuncSetAttribute(fused_mlp_v15,
                         cudaFuncAttributeMaxDynamicSharedMemorySize, SMEM_TOTAL);
    fused_mlp_v15<<<M / BM, THREADS, SMEM_TOTAL>>>(x, b0, b1, b2, out);
}